// round 3
// baseline (speedup 1.0000x reference)
#include <cuda_runtime.h>
#include <math.h>

// ---------------- problem constants ----------------
#define Bn   16
#define NMm  80
#define Tt   4000
#define Cc   512
#define Hh   8
#define DHd  64
#define Ll   4
#define DFFf 2048
#define NCc  8
#define TP   2000            // Tp after stride-2 conv
#define MTOK (Bn * TP)       // 32000 tokens

// ---------------- scratch (device globals; no cudaMalloc allowed) ----------------
__device__ float g_h[MTOK * Cc];           // residual stream   [B,Tp,C]
__device__ float g_hn[MTOK * Cc];          // LN output         [B,Tp,C]
__device__ float g_qkv[MTOK * 3 * Cc];     // qkv projections   [B,Tp,3C]
__device__ float g_ff[MTOK * DFFf];        // FFN hidden        [B,Tp,DFF]
__device__ float g_y[MTOK * Cc];           // attention output  [B,Tp,C]
__device__ float g_kv[Bn * Hh * DHd * DHd];// per-head KV state [B,H,64,64]
__device__ float g_z[Bn * Hh * DHd];       // per-head z        [B,H,64]
__device__ float g_pool[Bn * Cc];          // pooled features   [B,C]

__device__ __forceinline__ float gelu_f(float x) {
    return 0.5f * x * (1.0f + erff(x * 0.70710678118654752f));
}

// ---------------- conv(k3,s2,p1) + BN(eval) + GELU + PE, writes g_h [B,Tp,C] ----------------
__global__ __launch_bounds__(256) void conv_bn_gelu_pe(
    const float* __restrict__ x, const float* __restrict__ w,
    const float* __restrict__ bng, const float* __restrict__ bnb)
{
    __shared__ float xs[NMm][65];           // input window for 32 outputs: 2*32+1 = 65 samples
    const int b   = blockIdx.y;
    const int t0  = blockIdx.x * 32;
    const int tid = threadIdx.x;
    const int p0  = 2 * t0 - 1;             // pad=1

    for (int i = tid; i < NMm * 65; i += 256) {
        int m = i / 65, off = i % 65;
        int pos = p0 + off;
        float v = 0.f;
        if (pos >= 0 && pos < Tt) v = x[((size_t)b * NMm + m) * Tt + pos];
        xs[m][off] = v;
    }
    __syncthreads();

    const float LOG1E4 = 9.210340371976184f;  // ln(10000)
    for (int c = tid; c < Cc; c += 256) {
        float acc[32];
        #pragma unroll
        for (int t = 0; t < 32; t++) acc[t] = 0.f;
        const float* wc = w + (size_t)c * NMm * 3;
        for (int m = 0; m < NMm; m++) {
            float w0 = wc[m * 3 + 0], w1 = wc[m * 3 + 1], w2 = wc[m * 3 + 2];
            #pragma unroll
            for (int t = 0; t < 32; t++) {
                acc[t] += w0 * xs[m][2 * t] + w1 * xs[m][2 * t + 1] + w2 * xs[m][2 * t + 2];
            }
        }
        float scale = bng[c] * rsqrtf(1.0f + 1e-5f);
        float bias  = bnb[c];
        float freq  = expf(-(float)(c & ~1) * (LOG1E4 / (float)Cc));
        #pragma unroll
        for (int t = 0; t < 32; t++) {
            int tp = t0 + t;
            if (tp < TP) {
                float v = acc[t] * scale + bias;
                v = gelu_f(v);
                float ang = (float)tp * freq;
                v += (c & 1) ? cosf(ang) : sinf(ang);
                g_h[((size_t)b * TP + tp) * Cc + c] = v;
            }
        }
    }
}

// ---------------- LayerNorm over C=512, one block (128 thr) per token ----------------
__global__ __launch_bounds__(128) void ln_kernel(
    const float* __restrict__ in, const float* __restrict__ g,
    const float* __restrict__ bb, float* __restrict__ out)
{
    const int tok = blockIdx.x;
    const int tid = threadIdx.x;
    const float* row = in + (size_t)tok * Cc;
    float4 v = *(const float4*)(row + tid * 4);
    float s  = v.x + v.y + v.z + v.w;
    float s2 = v.x * v.x + v.y * v.y + v.z * v.z + v.w * v.w;
    #pragma unroll
    for (int off = 16; off; off >>= 1) {
        s  += __shfl_xor_sync(0xffffffffu, s,  off);
        s2 += __shfl_xor_sync(0xffffffffu, s2, off);
    }
    __shared__ float ss[4], ssq[4];
    if ((tid & 31) == 0) { ss[tid >> 5] = s; ssq[tid >> 5] = s2; }
    __syncthreads();
    s  = ss[0] + ss[1] + ss[2] + ss[3];
    s2 = ssq[0] + ssq[1] + ssq[2] + ssq[3];
    float mean = s * (1.0f / Cc);
    float var  = s2 * (1.0f / Cc) - mean * mean;
    float rstd = rsqrtf(var + 1e-5f);
    int cb = tid * 4;
    float4 o;
    o.x = (v.x - mean) * rstd * g[cb + 0] + bb[cb + 0];
    o.y = (v.y - mean) * rstd * g[cb + 1] + bb[cb + 1];
    o.z = (v.z - mean) * rstd * g[cb + 2] + bb[cb + 2];
    o.w = (v.w - mean) * rstd * g[cb + 3] + bb[cb + 3];
    *(float4*)(out + (size_t)tok * Cc + cb) = o;
}

// ---------------- fp32 NT GEMM: C[M,N] = A[M,K] @ B[N,K]^T (+bias, opt GELU, opt +=C) ----------------
// 128x128 tile, BK=8, 256 threads, 8x8 per thread, double-buffered smem.
// Requires M%128==0, N%128==0, K%16==0.
template <int ACT, int RES>
__global__ __launch_bounds__(256) void gemm_nt(
    const float* __restrict__ A, const float* __restrict__ B,
    const float* __restrict__ bias, float* __restrict__ C,
    int M, int N, int K)
{
    __shared__ float As[2][8][128];
    __shared__ float Bs[2][8][128];
    const int tid = threadIdx.x;
    const int m0 = blockIdx.y * 128, n0 = blockIdx.x * 128;
    const int lr = tid >> 1;            // 0..127
    const int lc = (tid & 1) << 2;      // 0 or 4
    const float* Ag = A + (size_t)(m0 + lr) * K + lc;
    const float* Bg = B + (size_t)(n0 + lr) * K + lc;
    const int tm = (tid >> 4) << 3;     // 0..120
    const int tn = (tid & 15) << 3;     // 0..120

    float acc[8][8];
    #pragma unroll
    for (int i = 0; i < 8; i++)
        #pragma unroll
        for (int j = 0; j < 8; j++) acc[i][j] = 0.f;

    // preload k-tile 0 into buffer 0
    {
        float4 a4 = *(const float4*)(Ag);
        float4 b4 = *(const float4*)(Bg);
        As[0][lc + 0][lr] = a4.x; As[0][lc + 1][lr] = a4.y;
        As[0][lc + 2][lr] = a4.z; As[0][lc + 3][lr] = a4.w;
        Bs[0][lc + 0][lr] = b4.x; Bs[0][lc + 1][lr] = b4.y;
        Bs[0][lc + 2][lr] = b4.z; Bs[0][lc + 3][lr] = b4.w;
    }
    __syncthreads();

    int buf = 0;
    for (int k0 = 8; k0 < K; k0 += 8) {
        // issue next tile's global loads early (latency overlapped with compute below)
        float4 a4 = *(const float4*)(Ag + k0);
        float4 b4 = *(const float4*)(Bg + k0);

        #pragma unroll
        for (int kk = 0; kk < 8; kk++) {
            float a[8], bw[8];
            *(float4*)(a)      = *(const float4*)(&As[buf][kk][tm]);
            *(float4*)(a + 4)  = *(const float4*)(&As[buf][kk][tm + 4]);
            *(float4*)(bw)     = *(const float4*)(&Bs[buf][kk][tn]);
            *(float4*)(bw + 4) = *(const float4*)(&Bs[buf][kk][tn + 4]);
            #pragma unroll
            for (int i = 0; i < 8; i++)
                #pragma unroll
                for (int j = 0; j < 8; j++)
                    acc[i][j] += a[i] * bw[j];
        }

        const int nb = buf ^ 1;
        As[nb][lc + 0][lr] = a4.x; As[nb][lc + 1][lr] = a4.y;
        As[nb][lc + 2][lr] = a4.z; As[nb][lc + 3][lr] = a4.w;
        Bs[nb][lc + 0][lr] = b4.x; Bs[nb][lc + 1][lr] = b4.y;
        Bs[nb][lc + 2][lr] = b4.z; Bs[nb][lc + 3][lr] = b4.w;
        __syncthreads();
        buf = nb;
    }

    // last tile
    #pragma unroll
    for (int kk = 0; kk < 8; kk++) {
        float a[8], bw[8];
        *(float4*)(a)      = *(const float4*)(&As[buf][kk][tm]);
        *(float4*)(a + 4)  = *(const float4*)(&As[buf][kk][tm + 4]);
        *(float4*)(bw)     = *(const float4*)(&Bs[buf][kk][tn]);
        *(float4*)(bw + 4) = *(const float4*)(&Bs[buf][kk][tn + 4]);
        #pragma unroll
        for (int i = 0; i < 8; i++)
            #pragma unroll
            for (int j = 0; j < 8; j++)
                acc[i][j] += a[i] * bw[j];
    }

    #pragma unroll
    for (int i = 0; i < 8; i++) {
        float* Crow = C + (size_t)(m0 + tm + i) * N + n0 + tn;
        #pragma unroll
        for (int j = 0; j < 8; j += 4) {
            float4 v;
            v.x = acc[i][j + 0] + bias[n0 + tn + j + 0];
            v.y = acc[i][j + 1] + bias[n0 + tn + j + 1];
            v.z = acc[i][j + 2] + bias[n0 + tn + j + 2];
            v.w = acc[i][j + 3] + bias[n0 + tn + j + 3];
            if (ACT) { v.x = gelu_f(v.x); v.y = gelu_f(v.y); v.z = gelu_f(v.z); v.w = gelu_f(v.w); }
            if (RES) {
                float4 o = *(const float4*)(Crow + j);
                v.x += o.x; v.y += o.y; v.z += o.z; v.w += o.w;
            }
            *(float4*)(Crow + j) = v;
        }
    }
}

// ---------------- linear-attention state: kv[d,e] = sum_t kf*v ; z[d] = sum_t kf ----------------
// grid = B*H blocks, 256 threads; chunks of 32 timesteps staged in smem.
__global__ __launch_bounds__(256) void attn_kv(const int* __restrict__ lengths)
{
    const int bh = blockIdx.x;
    const int b = bh >> 3, hd = bh & 7;
    const int lenb = (lengths[b] + 1) >> 1;
    __shared__ float kfs[32][64];
    __shared__ float vsm[32][64];
    const int tid = threadIdx.x;
    const int d0 = (tid & 15) << 2, e0 = (tid >> 4) << 2;

    float acc[4][4];
    float zacc[4];
    #pragma unroll
    for (int i = 0; i < 4; i++) {
        zacc[i] = 0.f;
        #pragma unroll
        for (int j = 0; j < 4; j++) acc[i][j] = 0.f;
    }

    for (int t0 = 0; t0 < TP; t0 += 32) {
        __syncthreads();
        for (int i = tid; i < 2048; i += 256) {
            int t = t0 + (i >> 6);
            int d = i & 63;
            float kf = 0.f, vv = 0.f;
            if (t < lenb) {   // lenb <= TP, so this also guards t < TP
                const float* row = g_qkv + ((size_t)(b * TP + t)) * 1536 + hd * 64;
                float kr = row[512 + d];
                kf = (kr > 0.f) ? kr + 1.f : expf(kr);   // elu(k)+1
                vv = row[1024 + d];
            }
            kfs[i >> 6][d] = kf;
            vsm[i >> 6][d] = vv;
        }
        __syncthreads();
        for (int t = 0; t < 32; t++) {
            float kf4[4], v4[4];
            *(float4*)kf4 = *(const float4*)&kfs[t][d0];
            *(float4*)v4  = *(const float4*)&vsm[t][e0];
            #pragma unroll
            for (int i = 0; i < 4; i++)
                #pragma unroll
                for (int j = 0; j < 4; j++)
                    acc[i][j] += kf4[i] * v4[j];
            if (e0 == 0) {
                #pragma unroll
                for (int i = 0; i < 4; i++) zacc[i] += kf4[i];
            }
        }
    }

    float* kvp = g_kv + (size_t)bh * 4096;
    #pragma unroll
    for (int i = 0; i < 4; i++)
        #pragma unroll
        for (int j = 0; j < 4; j++)
            kvp[(d0 + i) * 64 + e0 + j] = acc[i][j];
    if (e0 == 0) {
        #pragma unroll
        for (int i = 0; i < 4; i++) g_z[bh * 64 + d0 + i] = zacc[i];
    }
}

// ---------------- y[t,h,:] = (qf @ kv) / max(qf.z, eps) ; grid (63, B*H), 256 thr ----------------
__global__ __launch_bounds__(256) void attn_y()
{
    const int bh = blockIdx.y;
    const int b = bh >> 3, hd = bh & 7;
    const int t0 = blockIdx.x * 32;
    __shared__ float kvs[4096];
    __shared__ float zs[64];
    for (int i = threadIdx.x; i < 4096; i += 256) kvs[i] = g_kv[(size_t)bh * 4096 + i];
    if (threadIdx.x < 64) zs[threadIdx.x] = g_z[bh * 64 + threadIdx.x];
    __syncthreads();

    const int warp = threadIdx.x >> 5, lane = threadIdx.x & 31;
    for (int tt = 0; tt < 4; tt++) {
        int t = t0 + warp + (tt << 3);
        if (t >= TP) continue;
        const float* row = g_qkv + (size_t)(b * TP + t) * 1536 + hd * 64;
        float qa = row[lane];
        qa = (qa > 0.f) ? qa + 1.f : expf(qa);
        float qb = row[lane + 32];
        qb = (qb > 0.f) ? qb + 1.f : expf(qb);

        float den = qa * zs[lane] + qb * zs[lane + 32];
        #pragma unroll
        for (int off = 16; off; off >>= 1) den += __shfl_xor_sync(0xffffffffu, den, off);
        den = fmaxf(den, 1e-6f);
        float inv = 1.0f / den;

        float n0 = 0.f, n1 = 0.f;
        #pragma unroll
        for (int d = 0; d < 32; d++) {
            float qv = __shfl_sync(0xffffffffu, qa, d);
            n0 += qv * kvs[d * 64 + lane];
            n1 += qv * kvs[d * 64 + 32 + lane];
        }
        #pragma unroll
        for (int d = 0; d < 32; d++) {
            float qv = __shfl_sync(0xffffffffu, qb, d);
            n0 += qv * kvs[(d + 32) * 64 + lane];
            n1 += qv * kvs[(d + 32) * 64 + 32 + lane];
        }
        float* yrow = g_y + (size_t)(b * TP + t) * Cc + hd * 64;
        yrow[lane]      = n0 * inv;
        yrow[lane + 32] = n1 * inv;
    }
}

// ---------------- masked mean pool over time ----------------
__global__ __launch_bounds__(512) void pool_kernel(const int* __restrict__ lengths)
{
    const int b = blockIdx.x, c = threadIdx.x;
    const int lenb = (lengths[b] + 1) >> 1;   // >= 1
    const float* p = g_h + (size_t)b * TP * Cc + c;
    float s = 0.f;
    for (int t = 0; t < lenb; t++) s += p[(size_t)t * Cc];
    g_pool[b * Cc + c] = s / (float)lenb;
}

// ---------------- final FC: out[b,n] = pooled[b] . fc_w[n] + fc_b[n] ----------------
__global__ __launch_bounds__(128) void fc_kernel(
    const float* __restrict__ fw, const float* __restrict__ fb, float* __restrict__ out)
{
    const int tid = threadIdx.x;            // 128 = 16*8
    const int b = tid >> 3, n = tid & 7;
    const float* p  = g_pool + b * Cc;
    const float* wr = fw + n * Cc;
    float acc = 0.f;
    for (int k = 0; k < Cc; k++) acc += p[k] * wr[k];
    out[b * NCc + n] = acc + fb[n];
}

// ---------------- launch ----------------
extern "C" void kernel_launch(void* const* d_in, const int* in_sizes, int n_in,
                              void* d_out, int out_size)
{
    (void)in_sizes; (void)n_in; (void)out_size;
    const float* x       = (const float*)d_in[0];
    const int*   lengths = (const int*)  d_in[1];
    const float* conv_w  = (const float*)d_in[2];
    const float* bn_g    = (const float*)d_in[3];
    const float* bn_b    = (const float*)d_in[4];
    const float* qkv_w   = (const float*)d_in[5];
    const float* qkv_b   = (const float*)d_in[6];
    const float* out_w   = (const float*)d_in[7];
    const float* out_b   = (const float*)d_in[8];
    const float* lin1_w  = (const float*)d_in[9];
    const float* lin1_b  = (const float*)d_in[10];
    const float* lin2_w  = (const float*)d_in[11];
    const float* lin2_b  = (const float*)d_in[12];
    const float* ln1_g   = (const float*)d_in[13];
    const float* ln1_b   = (const float*)d_in[14];
    const float* ln2_g   = (const float*)d_in[15];
    const float* ln2_b   = (const float*)d_in[16];
    const float* fc_w    = (const float*)d_in[17];
    const float* fc_b    = (const float*)d_in[18];
    float* out = (float*)d_out;

    float *h, *hn, *qkv, *ff, *y;
    cudaGetSymbolAddress((void**)&h,   g_h);
    cudaGetSymbolAddress((void**)&hn,  g_hn);
    cudaGetSymbolAddress((void**)&qkv, g_qkv);
    cudaGetSymbolAddress((void**)&ff,  g_ff);
    cudaGetSymbolAddress((void**)&y,   g_y);

    // conv + BN + GELU + positional encoding -> g_h
    conv_bn_gelu_pe<<<dim3(63, Bn), 256>>>(x, conv_w, bn_g, bn_b);

    for (int l = 0; l < Ll; l++) {
        // --- pre-norm linear attention ---
        ln_kernel<<<MTOK, 128>>>(h, ln1_g + l * Cc, ln1_b + l * Cc, hn);
        gemm_nt<0, 0><<<dim3(12, 250), 256>>>(hn, qkv_w + (size_t)l * 3 * Cc * Cc,
                                              qkv_b + (size_t)l * 3 * Cc, qkv,
                                              MTOK, 3 * Cc, Cc);
        attn_kv<<<Bn * Hh, 256>>>(lengths);
        attn_y<<<dim3(63, Bn * Hh), 256>>>();
        gemm_nt<0, 1><<<dim3(4, 250), 256>>>(y, out_w + (size_t)l * Cc * Cc,
                                             out_b + (size_t)l * Cc, h,
                                             MTOK, Cc, Cc);        // h += proj(y)
        // --- pre-norm FFN ---
        ln_kernel<<<MTOK, 128>>>(h, ln2_g + l * Cc, ln2_b + l * Cc, hn);
        gemm_nt<1, 0><<<dim3(16, 250), 256>>>(hn, lin1_w + (size_t)l * DFFf * Cc,
                                              lin1_b + (size_t)l * DFFf, ff,
                                              MTOK, DFFf, Cc);     // gelu fused
        gemm_nt<0, 1><<<dim3(4, 250), 256>>>(ff, lin2_w + (size_t)l * Cc * DFFf,
                                             lin2_b + (size_t)l * Cc, h,
                                             MTOK, Cc, DFFf);      // h += ffn
    }

    pool_kernel<<<Bn, 512>>>(lengths);
    fc_kernel<<<1, 128>>>(fc_w, fc_b, out);
}

// round 6
// speedup vs baseline: 1.0434x; 1.0434x over previous
#include <cuda_runtime.h>
#include <math.h>

// ---------------- problem constants ----------------
#define Bn   16
#define NMm  80
#define Tt   4000
#define Cc   512
#define Hh   8
#define DHd  64
#define Ll   4
#define DFFf 2048
#define NCc  8
#define TP   2000            // Tp after stride-2 conv
#define MTOK (Bn * TP)       // 32000 tokens
#define KVCH 8               // time chunks for attn_kv
#define KVCS 256             // chunk size (covers TP=2000 with 8 chunks)

// ---------------- scratch (device globals; no cudaMalloc allowed) ----------------
__device__ float g_h[MTOK * Cc];           // residual stream   [B,Tp,C]
__device__ float g_hn[MTOK * Cc];          // LN output         [B,Tp,C]
__device__ float g_qkv[MTOK * 3 * Cc];     // qkv projections   [B,Tp,3C]
__device__ float g_ff[MTOK * DFFf];        // FFN hidden        [B,Tp,DFF]
__device__ float g_y[MTOK * Cc];           // attention output  [B,Tp,C]
__device__ float g_kv[Bn * Hh * DHd * DHd];// per-head KV state [B,H,64,64]
__device__ float g_z[Bn * Hh * DHd];       // per-head z        [B,H,64]
__device__ float g_kvp[KVCH][Bn * Hh][DHd * DHd]; // partial KV
__device__ float g_zp[KVCH][Bn * Hh][DHd];        // partial z
__device__ float g_pool[Bn * Cc];          // pooled features   [B,C]

__device__ __forceinline__ float gelu_f(float x) {
    return 0.5f * x * (1.0f + erff(x * 0.70710678118654752f));
}

// packed f32x2 helpers (sm_100+ dual-FMA pipe)
__device__ __forceinline__ void ffma2(unsigned long long& d, unsigned long long a, unsigned long long b) {
    asm("fma.rn.f32x2 %0, %1, %2, %0;" : "+l"(d) : "l"(a), "l"(b));
}
__device__ __forceinline__ unsigned long long pack2(float x) {
    unsigned long long r;
    unsigned int xi = __float_as_uint(x);
    asm("mov.b64 %0, {%1, %1};" : "=l"(r) : "r"(xi));
    return r;
}

// ---------------- conv(k3,s2,p1) + BN(eval) + GELU + PE, writes g_h [B,Tp,C] ----------------
__global__ __launch_bounds__(256) void conv_bn_gelu_pe(
    const float* __restrict__ x, const float* __restrict__ w,
    const float* __restrict__ bng, const float* __restrict__ bnb)
{
    __shared__ float xs[NMm][65];           // input window for 32 outputs: 2*32+1 = 65 samples
    const int b   = blockIdx.y;
    const int t0  = blockIdx.x * 32;
    const int tid = threadIdx.x;
    const int p0  = 2 * t0 - 1;             // pad=1

    for (int i = tid; i < NMm * 65; i += 256) {
        int m = i / 65, off = i % 65;
        int pos = p0 + off;
        float v = 0.f;
        if (pos >= 0 && pos < Tt) v = x[((size_t)b * NMm + m) * Tt + pos];
        xs[m][off] = v;
    }
    __syncthreads();

    const float LOG1E4 = 9.210340371976184f;  // ln(10000)
    for (int c = tid; c < Cc; c += 256) {
        float acc[32];
        #pragma unroll
        for (int t = 0; t < 32; t++) acc[t] = 0.f;
        const float* wc = w + (size_t)c * NMm * 3;
        for (int m = 0; m < NMm; m++) {
            float w0 = wc[m * 3 + 0], w1 = wc[m * 3 + 1], w2 = wc[m * 3 + 2];
            #pragma unroll
            for (int t = 0; t < 32; t++) {
                acc[t] += w0 * xs[m][2 * t] + w1 * xs[m][2 * t + 1] + w2 * xs[m][2 * t + 2];
            }
        }
        float scale = bng[c] * rsqrtf(1.0f + 1e-5f);
        float bias  = bnb[c];
        float freq  = expf(-(float)(c & ~1) * (LOG1E4 / (float)Cc));
        #pragma unroll
        for (int t = 0; t < 32; t++) {
            int tp = t0 + t;
            if (tp < TP) {
                float v = acc[t] * scale + bias;
                v = gelu_f(v);
                float ang = (float)tp * freq;
                v += (c & 1) ? cosf(ang) : sinf(ang);
                g_h[((size_t)b * TP + tp) * Cc + c] = v;
            }
        }
    }
}

// ---------------- LayerNorm over C=512, one block (128 thr) per token ----------------
__global__ __launch_bounds__(128) void ln_kernel(
    const float* __restrict__ in, const float* __restrict__ g,
    const float* __restrict__ bb, float* __restrict__ out)
{
    const int tok = blockIdx.x;
    const int tid = threadIdx.x;
    const float* row = in + (size_t)tok * Cc;
    float4 v = *(const float4*)(row + tid * 4);
    float s  = v.x + v.y + v.z + v.w;
    float s2 = v.x * v.x + v.y * v.y + v.z * v.z + v.w * v.w;
    #pragma unroll
    for (int off = 16; off; off >>= 1) {
        s  += __shfl_xor_sync(0xffffffffu, s,  off);
        s2 += __shfl_xor_sync(0xffffffffu, s2, off);
    }
    __shared__ float ss[4], ssq[4];
    if ((tid & 31) == 0) { ss[tid >> 5] = s; ssq[tid >> 5] = s2; }
    __syncthreads();
    s  = ss[0] + ss[1] + ss[2] + ss[3];
    s2 = ssq[0] + ssq[1] + ssq[2] + ssq[3];
    float mean = s * (1.0f / Cc);
    float var  = s2 * (1.0f / Cc) - mean * mean;
    float rstd = rsqrtf(var + 1e-5f);
    int cb = tid * 4;
    float4 o;
    o.x = (v.x - mean) * rstd * g[cb + 0] + bb[cb + 0];
    o.y = (v.y - mean) * rstd * g[cb + 1] + bb[cb + 1];
    o.z = (v.z - mean) * rstd * g[cb + 2] + bb[cb + 2];
    o.w = (v.w - mean) * rstd * g[cb + 3] + bb[cb + 3];
    *(float4*)(out + (size_t)tok * Cc + cb) = o;
}

// ---------------- fp32 NT GEMM: C[M,N] = A[M,K] @ B[N,K]^T (+bias, opt GELU, opt +=C) ----------------
// 128x128 tile, BK=8, 256 threads, 8x8 per thread, double-buffered smem,
// packed fma.rn.f32x2 inner loop. Requires M%128==0, N%128==0, K%16==0.
template <int ACT, int RES>
__global__ __launch_bounds__(256) void gemm_nt(
    const float* __restrict__ A, const float* __restrict__ B,
    const float* __restrict__ bias, float* __restrict__ C,
    int M, int N, int K)
{
    __shared__ float As[2][8][128];
    __shared__ float Bs[2][8][128];
    const int tid = threadIdx.x;
    const int m0 = blockIdx.y * 128, n0 = blockIdx.x * 128;
    const int lr = tid >> 1;            // 0..127
    const int lc = (tid & 1) << 2;      // 0 or 4
    const float* Ag = A + (size_t)(m0 + lr) * K + lc;
    const float* Bg = B + (size_t)(n0 + lr) * K + lc;
    const int tm = (tid >> 4) << 3;     // 0..120
    const int tn = (tid & 15) << 3;     // 0..120

    // accumulators as packed f32x2 pairs: accp[i][j] = columns (tn+2j, tn+2j+1)
    unsigned long long accp[8][4];
    #pragma unroll
    for (int i = 0; i < 8; i++)
        #pragma unroll
        for (int j = 0; j < 4; j++) accp[i][j] = 0ull;

    // preload k-tile 0 into buffer 0
    {
        float4 a4 = *(const float4*)(Ag);
        float4 b4 = *(const float4*)(Bg);
        As[0][lc + 0][lr] = a4.x; As[0][lc + 1][lr] = a4.y;
        As[0][lc + 2][lr] = a4.z; As[0][lc + 3][lr] = a4.w;
        Bs[0][lc + 0][lr] = b4.x; Bs[0][lc + 1][lr] = b4.y;
        Bs[0][lc + 2][lr] = b4.z; Bs[0][lc + 3][lr] = b4.w;
    }
    __syncthreads();

    int buf = 0;
    for (int k0 = 8; k0 < K; k0 += 8) {
        // issue next tile's global loads early (latency overlapped with compute below)
        float4 a4 = *(const float4*)(Ag + k0);
        float4 b4 = *(const float4*)(Bg + k0);

        #pragma unroll
        for (int kk = 0; kk < 8; kk++) {
            union { float4 v[2]; float f[8]; } au;
            union { float4 v[2]; unsigned long long p[4]; } bu;
            au.v[0] = *(const float4*)(&As[buf][kk][tm]);
            au.v[1] = *(const float4*)(&As[buf][kk][tm + 4]);
            bu.v[0] = *(const float4*)(&Bs[buf][kk][tn]);
            bu.v[1] = *(const float4*)(&Bs[buf][kk][tn + 4]);
            #pragma unroll
            for (int i = 0; i < 8; i++) {
                unsigned long long ap = pack2(au.f[i]);
                #pragma unroll
                for (int j = 0; j < 4; j++) ffma2(accp[i][j], ap, bu.p[j]);
            }
        }

        const int nb = buf ^ 1;
        As[nb][lc + 0][lr] = a4.x; As[nb][lc + 1][lr] = a4.y;
        As[nb][lc + 2][lr] = a4.z; As[nb][lc + 3][lr] = a4.w;
        Bs[nb][lc + 0][lr] = b4.x; Bs[nb][lc + 1][lr] = b4.y;
        Bs[nb][lc + 2][lr] = b4.z; Bs[nb][lc + 3][lr] = b4.w;
        __syncthreads();
        buf = nb;
    }

    // last tile
    #pragma unroll
    for (int kk = 0; kk < 8; kk++) {
        union { float4 v[2]; float f[8]; } au;
        union { float4 v[2]; unsigned long long p[4]; } bu;
        au.v[0] = *(const float4*)(&As[buf][kk][tm]);
        au.v[1] = *(const float4*)(&As[buf][kk][tm + 4]);
        bu.v[0] = *(const float4*)(&Bs[buf][kk][tn]);
        bu.v[1] = *(const float4*)(&Bs[buf][kk][tn + 4]);
        #pragma unroll
        for (int i = 0; i < 8; i++) {
            unsigned long long ap = pack2(au.f[i]);
            #pragma unroll
            for (int j = 0; j < 4; j++) ffma2(accp[i][j], ap, bu.p[j]);
        }
    }

    // epilogue
    float bsv[8];
    *(float4*)(bsv)     = *(const float4*)(bias + n0 + tn);
    *(float4*)(bsv + 4) = *(const float4*)(bias + n0 + tn + 4);

    #pragma unroll
    for (int i = 0; i < 8; i++) {
        float accr[8];
        #pragma unroll
        for (int j = 0; j < 4; j++) {
            union { unsigned long long u; float2 f2; } cv;
            cv.u = accp[i][j];
            accr[2 * j]     = cv.f2.x;
            accr[2 * j + 1] = cv.f2.y;
        }
        float* Crow = C + (size_t)(m0 + tm + i) * N + n0 + tn;
        #pragma unroll
        for (int j = 0; j < 8; j += 4) {
            float4 v;
            v.x = accr[j + 0] + bsv[j + 0];
            v.y = accr[j + 1] + bsv[j + 1];
            v.z = accr[j + 2] + bsv[j + 2];
            v.w = accr[j + 3] + bsv[j + 3];
            if (ACT) { v.x = gelu_f(v.x); v.y = gelu_f(v.y); v.z = gelu_f(v.z); v.w = gelu_f(v.w); }
            if (RES) {
                float4 o = *(const float4*)(Crow + j);
                v.x += o.x; v.y += o.y; v.z += o.z; v.w += o.w;
            }
            *(float4*)(Crow + j) = v;
        }
    }
}

// ---------------- linear-attention state partials over time chunks ----------------
// grid = (B*H, KVCH), 256 threads; each block reduces its chunk of timesteps.
__global__ __launch_bounds__(256) void attn_kv_partial(const int* __restrict__ lengths)
{
    const int bh = blockIdx.x;
    const int ch = blockIdx.y;
    const int b = bh >> 3, hd = bh & 7;
    const int lenb = (lengths[b] + 1) >> 1;
    const int c0 = ch * KVCS;
    const int c1 = (c0 + KVCS < TP) ? c0 + KVCS : TP;
    __shared__ float kfs[32][64];
    __shared__ float vsm[32][64];
    const int tid = threadIdx.x;
    const int d0 = (tid & 15) << 2, e0 = (tid >> 4) << 2;

    float acc[4][4];
    float zacc[4];
    #pragma unroll
    for (int i = 0; i < 4; i++) {
        zacc[i] = 0.f;
        #pragma unroll
        for (int j = 0; j < 4; j++) acc[i][j] = 0.f;
    }

    for (int t0 = c0; t0 < c1; t0 += 32) {
        __syncthreads();
        for (int i = tid; i < 2048; i += 256) {
            int t = t0 + (i >> 6);
            int d = i & 63;
            float kf = 0.f, vv = 0.f;
            if (t < lenb && t < c1) {     // lenb <= TP guards global reads
                const float* row = g_qkv + ((size_t)(b * TP + t)) * 1536 + hd * 64;
                float kr = row[512 + d];
                kf = (kr > 0.f) ? kr + 1.f : expf(kr);   // elu(k)+1
                vv = row[1024 + d];
            }
            kfs[i >> 6][d] = kf;
            vsm[i >> 6][d] = vv;
        }
        __syncthreads();
        #pragma unroll 8
        for (int t = 0; t < 32; t++) {
            float kf4[4], v4[4];
            *(float4*)kf4 = *(const float4*)&kfs[t][d0];
            *(float4*)v4  = *(const float4*)&vsm[t][e0];
            #pragma unroll
            for (int i = 0; i < 4; i++)
                #pragma unroll
                for (int j = 0; j < 4; j++)
                    acc[i][j] += kf4[i] * v4[j];
            if (e0 == 0) {
                #pragma unroll
                for (int i = 0; i < 4; i++) zacc[i] += kf4[i];
            }
        }
    }

    float* kvp = g_kvp[ch][bh];
    #pragma unroll
    for (int i = 0; i < 4; i++)
        #pragma unroll
        for (int j = 0; j < 4; j++)
            kvp[(d0 + i) * 64 + e0 + j] = acc[i][j];
    if (e0 == 0) {
        #pragma unroll
        for (int i = 0; i < 4; i++) g_zp[ch][bh][d0 + i] = zacc[i];
    }
}

// deterministic fixed-order reduction of chunk partials
__global__ __launch_bounds__(256) void attn_kv_reduce()
{
    const int bh = blockIdx.x;
    const int tid = threadIdx.x;
    for (int i = tid; i < DHd * DHd; i += 256) {
        float s = 0.f;
        #pragma unroll
        for (int c = 0; c < KVCH; c++) s += g_kvp[c][bh][i];
        g_kv[(size_t)bh * 4096 + i] = s;
    }
    if (tid < DHd) {
        float s = 0.f;
        #pragma unroll
        for (int c = 0; c < KVCH; c++) s += g_zp[c][bh][tid];
        g_z[bh * DHd + tid] = s;
    }
}

// ---------------- y[t,h,:] = (qf @ kv) / max(qf.z, eps) ; grid (63, B*H), 256 thr ----------------
__global__ __launch_bounds__(256) void attn_y()
{
    const int bh = blockIdx.y;
    const int b = bh >> 3, hd = bh & 7;
    const int t0 = blockIdx.x * 32;
    __shared__ float kvs[4096];
    __shared__ float zs[64];
    for (int i = threadIdx.x; i < 4096; i += 256) kvs[i] = g_kv[(size_t)bh * 4096 + i];
    if (threadIdx.x < 64) zs[threadIdx.x] = g_z[bh * 64 + threadIdx.x];
    __syncthreads();

    const int warp = threadIdx.x >> 5, lane = threadIdx.x & 31;
    for (int tt = 0; tt < 4; tt++) {
        int t = t0 + warp + (tt << 3);
        if (t >= TP) continue;
        const float* row = g_qkv + (size_t)(b * TP + t) * 1536 + hd * 64;
        float qa = row[lane];
        qa = (qa > 0.f) ? qa + 1.f : expf(qa);
        float qb = row[lane + 32];
        qb = (qb > 0.f) ? qb + 1.f : expf(qb);

        float den = qa * zs[lane] + qb * zs[lane + 32];
        #pragma unroll
        for (int off = 16; off; off >>= 1) den += __shfl_xor_sync(0xffffffffu, den, off);
        den = fmaxf(den, 1e-6f);
        float inv = 1.0f / den;

        float n0 = 0.f, n1 = 0.f;
        #pragma unroll
        for (int d = 0; d < 32; d++) {
            float qv = __shfl_sync(0xffffffffu, qa, d);
            n0 += qv * kvs[d * 64 + lane];
            n1 += qv * kvs[d * 64 + 32 + lane];
        }
        #pragma unroll
        for (int d = 0; d < 32; d++) {
            float qv = __shfl_sync(0xffffffffu, qb, d);
            n0 += qv * kvs[(d + 32) * 64 + lane];
            n1 += qv * kvs[(d + 32) * 64 + 32 + lane];
        }
        float* yrow = g_y + (size_t)(b * TP + t) * Cc + hd * 64;
        yrow[lane]      = n0 * inv;
        yrow[lane + 32] = n1 * inv;
    }
}

// ---------------- masked mean pool over time ----------------
__global__ __launch_bounds__(512) void pool_kernel(const int* __restrict__ lengths)
{
    const int b = blockIdx.x, c = threadIdx.x;
    const int lenb = (lengths[b] + 1) >> 1;   // >= 1
    const float* p = g_h + (size_t)b * TP * Cc + c;
    float s = 0.f;
    for (int t = 0; t < lenb; t++) s += p[(size_t)t * Cc];
    g_pool[b * Cc + c] = s / (float)lenb;
}

// ---------------- final FC: out[b,n] = pooled[b] . fc_w[n] + fc_b[n] ----------------
__global__ __launch_bounds__(128) void fc_kernel(
    const float* __restrict__ fw, const float* __restrict__ fb, float* __restrict__ out)
{
    const int tid = threadIdx.x;            // 128 = 16*8
    const int b = tid >> 3, n = tid & 7;
    const float* p  = g_pool + b * Cc;
    const float* wr = fw + n * Cc;
    float acc = 0.f;
    for (int k = 0; k < Cc; k++) acc += p[k] * wr[k];
    out[b * NCc + n] = acc + fb[n];
}

// ---------------- launch ----------------
extern "C" void kernel_launch(void* const* d_in, const int* in_sizes, int n_in,
                              void* d_out, int out_size)
{
    (void)in_sizes; (void)n_in; (void)out_size;
    const float* x       = (const float*)d_in[0];
    const int*   lengths = (const int*)  d_in[1];
    const float* conv_w  = (const float*)d_in[2];
    const float* bn_g    = (const float*)d_in[3];
    const float* bn_b    = (const float*)d_in[4];
    const float* qkv_w   = (const float*)d_in[5];
    const float* qkv_b   = (const float*)d_in[6];
    const float* out_w   = (const float*)d_in[7];
    const float* out_b   = (const float*)d_in[8];
    const float* lin1_w  = (const float*)d_in[9];
    const float* lin1_b  = (const float*)d_in[10];
    const float* lin2_w  = (const float*)d_in[11];
    const float* lin2_b  = (const float*)d_in[12];
    const float* ln1_g   = (const float*)d_in[13];
    const float* ln1_b   = (const float*)d_in[14];
    const float* ln2_g   = (const float*)d_in[15];
    const float* ln2_b   = (const float*)d_in[16];
    const float* fc_w    = (const float*)d_in[17];
    const float* fc_b    = (const float*)d_in[18];
    float* out = (float*)d_out;

    float *h, *hn, *qkv, *ff, *y;
    cudaGetSymbolAddress((void**)&h,   g_h);
    cudaGetSymbolAddress((void**)&hn,  g_hn);
    cudaGetSymbolAddress((void**)&qkv, g_qkv);
    cudaGetSymbolAddress((void**)&ff,  g_ff);
    cudaGetSymbolAddress((void**)&y,   g_y);

    // conv + BN + GELU + positional encoding -> g_h
    conv_bn_gelu_pe<<<dim3(63, Bn), 256>>>(x, conv_w, bn_g, bn_b);

    for (int l = 0; l < Ll; l++) {
        // --- pre-norm linear attention ---
        ln_kernel<<<MTOK, 128>>>(h, ln1_g + l * Cc, ln1_b + l * Cc, hn);
        gemm_nt<0, 0><<<dim3(12, 250), 256>>>(hn, qkv_w + (size_t)l * 3 * Cc * Cc,
                                              qkv_b + (size_t)l * 3 * Cc, qkv,
                                              MTOK, 3 * Cc, Cc);
        attn_kv_partial<<<dim3(Bn * Hh, KVCH), 256>>>(lengths);
        attn_kv_reduce<<<Bn * Hh, 256>>>();
        attn_y<<<dim3(63, Bn * Hh), 256>>>();
        gemm_nt<0, 1><<<dim3(4, 250), 256>>>(y, out_w + (size_t)l * Cc * Cc,
                                             out_b + (size_t)l * Cc, h,
                                             MTOK, Cc, Cc);        // h += proj(y)
        // --- pre-norm FFN ---
        ln_kernel<<<MTOK, 128>>>(h, ln2_g + l * Cc, ln2_b + l * Cc, hn);
        gemm_nt<1, 0><<<dim3(16, 250), 256>>>(hn, lin1_w + (size_t)l * DFFf * Cc,
                                              lin1_b + (size_t)l * DFFf, ff,
                                              MTOK, DFFf, Cc);     // gelu fused
        gemm_nt<0, 1><<<dim3(4, 250), 256>>>(ff, lin2_w + (size_t)l * Cc * DFFf,
                                             lin2_b + (size_t)l * Cc, h,
                                             MTOK, Cc, DFFf);      // h += ffn
    }

    pool_kernel<<<Bn, 512>>>(lengths);
    fc_kernel<<<1, 128>>>(fc_w, fc_b, out);
}

// round 10
// speedup vs baseline: 1.8668x; 1.7892x over previous
#include <cuda_runtime.h>
#include <cuda_fp16.h>
#include <stdint.h>
#include <math.h>

// ---------------- problem constants ----------------
#define Bn   16
#define NMm  80
#define Tt   4000
#define Cc   512
#define Hh   8
#define DHd  64
#define Ll   4
#define DFFf 2048
#define NCc  8
#define TP   2000            // Tp after stride-2 conv
#define MTOK (Bn * TP)       // 32000 tokens
#define KVCH 8               // time chunks for attn_kv
#define KVCS 256             // chunk size (covers TP=2000 with 8 chunks)
#define SPAD 24              // smem row stride in halves (conflict-free for frag loads)

// ---------------- scratch (device globals; no cudaMalloc allowed) ----------------
__device__ float g_h[MTOK * Cc];           // residual stream   [B,Tp,C]
__device__ float g_hn[MTOK * Cc];          // LN output         [B,Tp,C]
__device__ float g_qkv[MTOK * 3 * Cc];     // qkv projections   [B,Tp,3C]
__device__ float g_ff[MTOK * DFFf];        // FFN hidden        [B,Tp,DFF]
__device__ float g_y[MTOK * Cc];           // attention output  [B,Tp,C]
__device__ float g_kv[Bn * Hh * DHd * DHd];// per-head KV state [B,H,64,64]
__device__ float g_z[Bn * Hh * DHd];       // per-head z        [B,H,64]
__device__ float g_kvp[KVCH][Bn * Hh][DHd * DHd]; // partial KV
__device__ float g_zp[KVCH][Bn * Hh][DHd];        // partial z
__device__ float g_pool[Bn * Cc];          // pooled features   [B,C]

__device__ __forceinline__ float gelu_f(float x) {
    return 0.5f * x * (1.0f + erff(x * 0.70710678118654752f));
}

// ---------------- conv(k3,s2,p1) + BN(eval) + GELU + PE, writes g_h [B,Tp,C] ----------------
__global__ __launch_bounds__(256) void conv_bn_gelu_pe(
    const float* __restrict__ x, const float* __restrict__ w,
    const float* __restrict__ bng, const float* __restrict__ bnb)
{
    __shared__ float xs[NMm][65];           // input window for 32 outputs: 2*32+1 = 65 samples
    const int b   = blockIdx.y;
    const int t0  = blockIdx.x * 32;
    const int tid = threadIdx.x;
    const int p0  = 2 * t0 - 1;             // pad=1

    for (int i = tid; i < NMm * 65; i += 256) {
        int m = i / 65, off = i % 65;
        int pos = p0 + off;
        float v = 0.f;
        if (pos >= 0 && pos < Tt) v = x[((size_t)b * NMm + m) * Tt + pos];
        xs[m][off] = v;
    }
    __syncthreads();

    const float LOG1E4 = 9.210340371976184f;  // ln(10000)
    for (int c = tid; c < Cc; c += 256) {
        float acc[32];
        #pragma unroll
        for (int t = 0; t < 32; t++) acc[t] = 0.f;
        const float* wc = w + (size_t)c * NMm * 3;
        for (int m = 0; m < NMm; m++) {
            float w0 = wc[m * 3 + 0], w1 = wc[m * 3 + 1], w2 = wc[m * 3 + 2];
            #pragma unroll
            for (int t = 0; t < 32; t++) {
                acc[t] += w0 * xs[m][2 * t] + w1 * xs[m][2 * t + 1] + w2 * xs[m][2 * t + 2];
            }
        }
        float scale = bng[c] * rsqrtf(1.0f + 1e-5f);
        float bias  = bnb[c];
        float freq  = expf(-(float)(c & ~1) * (LOG1E4 / (float)Cc));
        #pragma unroll
        for (int t = 0; t < 32; t++) {
            int tp = t0 + t;
            if (tp < TP) {
                float v = acc[t] * scale + bias;
                v = gelu_f(v);
                float ang = (float)tp * freq;
                v += (c & 1) ? cosf(ang) : sinf(ang);
                g_h[((size_t)b * TP + tp) * Cc + c] = v;
            }
        }
    }
}

// ---------------- LayerNorm over C=512, one block (128 thr) per token ----------------
__global__ __launch_bounds__(128) void ln_kernel(
    const float* __restrict__ in, const float* __restrict__ g,
    const float* __restrict__ bb, float* __restrict__ out)
{
    const int tok = blockIdx.x;
    const int tid = threadIdx.x;
    const float* row = in + (size_t)tok * Cc;
    float4 v = *(const float4*)(row + tid * 4);
    float s  = v.x + v.y + v.z + v.w;
    float s2 = v.x * v.x + v.y * v.y + v.z * v.z + v.w * v.w;
    #pragma unroll
    for (int off = 16; off; off >>= 1) {
        s  += __shfl_xor_sync(0xffffffffu, s,  off);
        s2 += __shfl_xor_sync(0xffffffffu, s2, off);
    }
    __shared__ float ss[4], ssq[4];
    if ((tid & 31) == 0) { ss[tid >> 5] = s; ssq[tid >> 5] = s2; }
    __syncthreads();
    s  = ss[0] + ss[1] + ss[2] + ss[3];
    s2 = ssq[0] + ssq[1] + ssq[2] + ssq[3];
    float mean = s * (1.0f / Cc);
    float var  = s2 * (1.0f / Cc) - mean * mean;
    float rstd = rsqrtf(var + 1e-5f);
    int cb = tid * 4;
    float4 o;
    o.x = (v.x - mean) * rstd * g[cb + 0] + bb[cb + 0];
    o.y = (v.y - mean) * rstd * g[cb + 1] + bb[cb + 1];
    o.z = (v.z - mean) * rstd * g[cb + 2] + bb[cb + 2];
    o.w = (v.w - mean) * rstd * g[cb + 3] + bb[cb + 3];
    *(float4*)(out + (size_t)tok * Cc + cb) = o;
}

// ---------------- tensor-core NT GEMM with fp16 split (error-compensated) ----------------
// C[M,N] = A[M,K] @ B[N,K]^T (+bias, opt GELU, opt +=C). fp32 operands split into
// hi/lo fp16; per k16 chunk: hi*hi + hi*lo + lo*hi via mma.sync.m16n8k16, fp32 accum.
// 128x128 block tile, BK=16, 256 threads (2x4 warps, 64x32 warp tile).
// Requires M%128==0, N%128==0, K%16==0.

__device__ __forceinline__ void mma16816(float* c,
    uint32_t a0, uint32_t a1, uint32_t a2, uint32_t a3,
    uint32_t b0, uint32_t b1)
{
    asm volatile(
        "mma.sync.aligned.m16n8k16.row.col.f32.f16.f16.f32 "
        "{%0,%1,%2,%3}, {%4,%5,%6,%7}, {%8,%9}, {%0,%1,%2,%3};"
        : "+f"(c[0]), "+f"(c[1]), "+f"(c[2]), "+f"(c[3])
        : "r"(a0), "r"(a1), "r"(a2), "r"(a3), "r"(b0), "r"(b1));
}

__device__ __forceinline__ void split_store8(__half* hip, __half* lop, float4 v0, float4 v1)
{
    float v[8] = {v0.x, v0.y, v0.z, v0.w, v1.x, v1.y, v1.z, v1.w};
    #pragma unroll
    for (int i = 0; i < 8; i += 2) {
        __half h0 = __float2half_rn(v[i]);
        __half h1 = __float2half_rn(v[i + 1]);
        __half l0 = __float2half_rn(v[i]     - __half2float(h0));
        __half l1 = __float2half_rn(v[i + 1] - __half2float(h1));
        *(__half2*)(hip + i) = __halves2half2(h0, h1);
        *(__half2*)(lop + i) = __halves2half2(l0, l1);
    }
}

template <int ACT, int RES>
__global__ __launch_bounds__(256, 2) void gemm_nt_mma(
    const float* __restrict__ A, const float* __restrict__ B,
    const float* __restrict__ bias, float* __restrict__ C,
    int M, int N, int K)
{
    __shared__ __half sAh[128][SPAD], sAl[128][SPAD];
    __shared__ __half sBh[128][SPAD], sBl[128][SPAD];

    const int tid  = threadIdx.x;
    const int warp = tid >> 5, lane = tid & 31;
    const int wm = warp >> 2, wn = warp & 3;        // 2 x 4 warp grid
    const int m0 = blockIdx.y * 128, n0 = blockIdx.x * 128;
    const int g  = lane >> 2;                        // 0..7
    const int t2 = (lane & 3) << 1;                  // 0,2,4,6

    const int lr  = tid >> 1;                        // 0..127 (load row)
    const int lcb = (tid & 1) << 3;                  // 0 or 8 (load col base)
    const float* Ag = A + (size_t)(m0 + lr) * K + lcb;
    const float* Bg = B + (size_t)(n0 + lr) * K + lcb;

    float acc[4][4][4];
    #pragma unroll
    for (int mi = 0; mi < 4; mi++)
        #pragma unroll
        for (int ni = 0; ni < 4; ni++)
            #pragma unroll
            for (int r = 0; r < 4; r++) acc[mi][ni][r] = 0.f;

    for (int k0 = 0; k0 < K; k0 += 16) {
        float4 a0 = *(const float4*)(Ag + k0);
        float4 a1 = *(const float4*)(Ag + k0 + 4);
        float4 b0 = *(const float4*)(Bg + k0);
        float4 b1 = *(const float4*)(Bg + k0 + 4);
        __syncthreads();                       // previous compute done
        split_store8(&sAh[lr][lcb], &sAl[lr][lcb], a0, a1);
        split_store8(&sBh[lr][lcb], &sBl[lr][lcb], b0, b1);
        __syncthreads();

        // A fragments (hi and lo) for this warp's 4 m-tiles
        uint32_t ah[4][4], al[4][4];
        #pragma unroll
        for (int mi = 0; mi < 4; mi++) {
            int r = wm * 64 + mi * 16 + g;
            ah[mi][0] = *(const uint32_t*)&sAh[r    ][t2    ];
            ah[mi][1] = *(const uint32_t*)&sAh[r + 8][t2    ];
            ah[mi][2] = *(const uint32_t*)&sAh[r    ][t2 + 8];
            ah[mi][3] = *(const uint32_t*)&sAh[r + 8][t2 + 8];
            al[mi][0] = *(const uint32_t*)&sAl[r    ][t2    ];
            al[mi][1] = *(const uint32_t*)&sAl[r + 8][t2    ];
            al[mi][2] = *(const uint32_t*)&sAl[r    ][t2 + 8];
            al[mi][3] = *(const uint32_t*)&sAl[r + 8][t2 + 8];
        }

        #pragma unroll
        for (int ni = 0; ni < 4; ni++) {
            int n = wn * 32 + ni * 8 + g;
            uint32_t bh0 = *(const uint32_t*)&sBh[n][t2    ];
            uint32_t bh1 = *(const uint32_t*)&sBh[n][t2 + 8];
            uint32_t bl0 = *(const uint32_t*)&sBl[n][t2    ];
            uint32_t bl1 = *(const uint32_t*)&sBl[n][t2 + 8];
            #pragma unroll
            for (int mi = 0; mi < 4; mi++) {
                mma16816(acc[mi][ni], ah[mi][0], ah[mi][1], ah[mi][2], ah[mi][3], bh0, bh1);
                mma16816(acc[mi][ni], ah[mi][0], ah[mi][1], ah[mi][2], ah[mi][3], bl0, bl1);
                mma16816(acc[mi][ni], al[mi][0], al[mi][1], al[mi][2], al[mi][3], bh0, bh1);
            }
        }
    }

    // epilogue: c0,c1 -> (row g, cols t2..t2+1); c2,c3 -> (row g+8, same cols)
    #pragma unroll
    for (int mi = 0; mi < 4; mi++) {
        #pragma unroll
        for (int ni = 0; ni < 4; ni++) {
            int R0 = m0 + wm * 64 + mi * 16 + g;
            int CB = n0 + wn * 32 + ni * 8 + t2;
            float bx = bias[CB], by = bias[CB + 1];
            float2 p0, p1;
            p0.x = acc[mi][ni][0] + bx; p0.y = acc[mi][ni][1] + by;
            p1.x = acc[mi][ni][2] + bx; p1.y = acc[mi][ni][3] + by;
            if (ACT) {
                p0.x = gelu_f(p0.x); p0.y = gelu_f(p0.y);
                p1.x = gelu_f(p1.x); p1.y = gelu_f(p1.y);
            }
            float* c0p = C + (size_t)R0 * N + CB;
            float* c1p = C + (size_t)(R0 + 8) * N + CB;
            if (RES) {
                float2 o0 = *(const float2*)c0p;
                float2 o1 = *(const float2*)c1p;
                p0.x += o0.x; p0.y += o0.y;
                p1.x += o1.x; p1.y += o1.y;
            }
            *(float2*)c0p = p0;
            *(float2*)c1p = p1;
        }
    }
}

// ---------------- linear-attention state partials over time chunks ----------------
__global__ __launch_bounds__(256) void attn_kv_partial(const int* __restrict__ lengths)
{
    const int bh = blockIdx.x;
    const int ch = blockIdx.y;
    const int b = bh >> 3, hd = bh & 7;
    const int lenb = (lengths[b] + 1) >> 1;
    const int c0 = ch * KVCS;
    const int c1 = (c0 + KVCS < TP) ? c0 + KVCS : TP;
    __shared__ float kfs[32][64];
    __shared__ float vsm[32][64];
    const int tid = threadIdx.x;
    const int d0 = (tid & 15) << 2, e0 = (tid >> 4) << 2;

    float acc[4][4];
    float zacc[4];
    #pragma unroll
    for (int i = 0; i < 4; i++) {
        zacc[i] = 0.f;
        #pragma unroll
        for (int j = 0; j < 4; j++) acc[i][j] = 0.f;
    }

    for (int t0 = c0; t0 < c1; t0 += 32) {
        __syncthreads();
        for (int i = tid; i < 2048; i += 256) {
            int t = t0 + (i >> 6);
            int d = i & 63;
            float kf = 0.f, vv = 0.f;
            if (t < lenb && t < c1) {
                const float* row = g_qkv + ((size_t)(b * TP + t)) * 1536 + hd * 64;
                float kr = row[512 + d];
                kf = (kr > 0.f) ? kr + 1.f : expf(kr);   // elu(k)+1
                vv = row[1024 + d];
            }
            kfs[i >> 6][d] = kf;
            vsm[i >> 6][d] = vv;
        }
        __syncthreads();
        #pragma unroll 8
        for (int t = 0; t < 32; t++) {
            float kf4[4], v4[4];
            *(float4*)kf4 = *(const float4*)&kfs[t][d0];
            *(float4*)v4  = *(const float4*)&vsm[t][e0];
            #pragma unroll
            for (int i = 0; i < 4; i++)
                #pragma unroll
                for (int j = 0; j < 4; j++)
                    acc[i][j] += kf4[i] * v4[j];
            if (e0 == 0) {
                #pragma unroll
                for (int i = 0; i < 4; i++) zacc[i] += kf4[i];
            }
        }
    }

    float* kvp = g_kvp[ch][bh];
    #pragma unroll
    for (int i = 0; i < 4; i++)
        #pragma unroll
        for (int j = 0; j < 4; j++)
            kvp[(d0 + i) * 64 + e0 + j] = acc[i][j];
    if (e0 == 0) {
        #pragma unroll
        for (int i = 0; i < 4; i++) g_zp[ch][bh][d0 + i] = zacc[i];
    }
}

// deterministic fixed-order reduction of chunk partials
__global__ __launch_bounds__(256) void attn_kv_reduce()
{
    const int bh = blockIdx.x;
    const int tid = threadIdx.x;
    for (int i = tid; i < DHd * DHd; i += 256) {
        float s = 0.f;
        #pragma unroll
        for (int c = 0; c < KVCH; c++) s += g_kvp[c][bh][i];
        g_kv[(size_t)bh * 4096 + i] = s;
    }
    if (tid < DHd) {
        float s = 0.f;
        #pragma unroll
        for (int c = 0; c < KVCH; c++) s += g_zp[c][bh][tid];
        g_z[bh * DHd + tid] = s;
    }
}

// ---------------- y[t,h,:] = (qf @ kv) / max(qf.z, eps) ; grid (63, B*H), 256 thr ----------------
__global__ __launch_bounds__(256) void attn_y()
{
    const int bh = blockIdx.y;
    const int b = bh >> 3, hd = bh & 7;
    const int t0 = blockIdx.x * 32;
    __shared__ float kvs[4096];
    __shared__ float zs[64];
    for (int i = threadIdx.x; i < 4096; i += 256) kvs[i] = g_kv[(size_t)bh * 4096 + i];
    if (threadIdx.x < 64) zs[threadIdx.x] = g_z[bh * 64 + threadIdx.x];
    __syncthreads();

    const int warp = threadIdx.x >> 5, lane = threadIdx.x & 31;
    for (int tt = 0; tt < 4; tt++) {
        int t = t0 + warp + (tt << 3);
        if (t >= TP) continue;
        const float* row = g_qkv + (size_t)(b * TP + t) * 1536 + hd * 64;
        float qa = row[lane];
        qa = (qa > 0.f) ? qa + 1.f : expf(qa);
        float qb = row[lane + 32];
        qb = (qb > 0.f) ? qb + 1.f : expf(qb);

        float den = qa * zs[lane] + qb * zs[lane + 32];
        #pragma unroll
        for (int off = 16; off; off >>= 1) den += __shfl_xor_sync(0xffffffffu, den, off);
        den = fmaxf(den, 1e-6f);
        float inv = 1.0f / den;

        float n0 = 0.f, n1 = 0.f;
        #pragma unroll
        for (int d = 0; d < 32; d++) {
            float qv = __shfl_sync(0xffffffffu, qa, d);
            n0 += qv * kvs[d * 64 + lane];
            n1 += qv * kvs[d * 64 + 32 + lane];
        }
        #pragma unroll
        for (int d = 0; d < 32; d++) {
            float qv = __shfl_sync(0xffffffffu, qb, d);
            n0 += qv * kvs[(d + 32) * 64 + lane];
            n1 += qv * kvs[(d + 32) * 64 + 32 + lane];
        }
        float* yrow = g_y + (size_t)(b * TP + t) * Cc + hd * 64;
        yrow[lane]      = n0 * inv;
        yrow[lane + 32] = n1 * inv;
    }
}

// ---------------- masked mean pool over time ----------------
__global__ __launch_bounds__(512) void pool_kernel(const int* __restrict__ lengths)
{
    const int b = blockIdx.x, c = threadIdx.x;
    const int lenb = (lengths[b] + 1) >> 1;   // >= 1
    const float* p = g_h + (size_t)b * TP * Cc + c;
    float s = 0.f;
    for (int t = 0; t < lenb; t++) s += p[(size_t)t * Cc];
    g_pool[b * Cc + c] = s / (float)lenb;
}

// ---------------- final FC: out[b,n] = pooled[b] . fc_w[n] + fc_b[n] ----------------
__global__ __launch_bounds__(128) void fc_kernel(
    const float* __restrict__ fw, const float* __restrict__ fb, float* __restrict__ out)
{
    const int tid = threadIdx.x;            // 128 = 16*8
    const int b = tid >> 3, n = tid & 7;
    const float* p  = g_pool + b * Cc;
    const float* wr = fw + n * Cc;
    float acc = 0.f;
    for (int k = 0; k < Cc; k++) acc += p[k] * wr[k];
    out[b * NCc + n] = acc + fb[n];
}

// ---------------- launch ----------------
extern "C" void kernel_launch(void* const* d_in, const int* in_sizes, int n_in,
                              void* d_out, int out_size)
{
    (void)in_sizes; (void)n_in; (void)out_size;
    const float* x       = (const float*)d_in[0];
    const int*   lengths = (const int*)  d_in[1];
    const float* conv_w  = (const float*)d_in[2];
    const float* bn_g    = (const float*)d_in[3];
    const float* bn_b    = (const float*)d_in[4];
    const float* qkv_w   = (const float*)d_in[5];
    const float* qkv_b   = (const float*)d_in[6];
    const float* out_w   = (const float*)d_in[7];
    const float* out_b   = (const float*)d_in[8];
    const float* lin1_w  = (const float*)d_in[9];
    const float* lin1_b  = (const float*)d_in[10];
    const float* lin2_w  = (const float*)d_in[11];
    const float* lin2_b  = (const float*)d_in[12];
    const float* ln1_g   = (const float*)d_in[13];
    const float* ln1_b   = (const float*)d_in[14];
    const float* ln2_g   = (const float*)d_in[15];
    const float* ln2_b   = (const float*)d_in[16];
    const float* fc_w    = (const float*)d_in[17];
    const float* fc_b    = (const float*)d_in[18];
    float* out = (float*)d_out;

    float *h, *hn, *qkv, *ff, *y;
    cudaGetSymbolAddress((void**)&h,   g_h);
    cudaGetSymbolAddress((void**)&hn,  g_hn);
    cudaGetSymbolAddress((void**)&qkv, g_qkv);
    cudaGetSymbolAddress((void**)&ff,  g_ff);
    cudaGetSymbolAddress((void**)&y,   g_y);

    // conv + BN + GELU + positional encoding -> g_h
    conv_bn_gelu_pe<<<dim3(63, Bn), 256>>>(x, conv_w, bn_g, bn_b);

    for (int l = 0; l < Ll; l++) {
        // --- pre-norm linear attention ---
        ln_kernel<<<MTOK, 128>>>(h, ln1_g + l * Cc, ln1_b + l * Cc, hn);
        gemm_nt_mma<0, 0><<<dim3(12, 250), 256>>>(hn, qkv_w + (size_t)l * 3 * Cc * Cc,
                                                  qkv_b + (size_t)l * 3 * Cc, qkv,
                                                  MTOK, 3 * Cc, Cc);
        attn_kv_partial<<<dim3(Bn * Hh, KVCH), 256>>>(lengths);
        attn_kv_reduce<<<Bn * Hh, 256>>>();
        attn_y<<<dim3(63, Bn * Hh), 256>>>();
        gemm_nt_mma<0, 1><<<dim3(4, 250), 256>>>(y, out_w + (size_t)l * Cc * Cc,
                                                 out_b + (size_t)l * Cc, h,
                                                 MTOK, Cc, Cc);        // h += proj(y)
        // --- pre-norm FFN ---
        ln_kernel<<<MTOK, 128>>>(h, ln2_g + l * Cc, ln2_b + l * Cc, hn);
        gemm_nt_mma<1, 0><<<dim3(16, 250), 256>>>(hn, lin1_w + (size_t)l * DFFf * Cc,
                                                  lin1_b + (size_t)l * DFFf, ff,
                                                  MTOK, DFFf, Cc);     // gelu fused
        gemm_nt_mma<0, 1><<<dim3(4, 250), 256>>>(ff, lin2_w + (size_t)l * Cc * DFFf,
                                                 lin2_b + (size_t)l * Cc, h,
                                                 MTOK, Cc, DFFf);      // h += ffn
    }

    pool_kernel<<<Bn, 512>>>(lengths);
    fc_kernel<<<1, 128>>>(fc_w, fc_b, out);
}

// round 13
// speedup vs baseline: 2.1294x; 1.1407x over previous
#include <cuda_runtime.h>
#include <cuda_fp16.h>
#include <stdint.h>
#include <math.h>

// ---------------- problem constants ----------------
#define Bn   16
#define NMm  80
#define Tt   4000
#define Cc   512
#define Hh   8
#define DHd  64
#define Ll   4
#define DFFf 2048
#define NCc  8
#define TP   2000            // Tp after stride-2 conv
#define MTOK (Bn * TP)       // 32000 tokens
#define KVCH 8               // time chunks for attn_kv
#define KVCS 256             // chunk size
#define SPAD 24              // smem row stride in halves (conflict-free frag loads)

// ---------------- scratch (device globals; no cudaMalloc allowed) ----------------
__device__ float g_h[MTOK * Cc];            // residual stream   [B,Tp,C]
__device__ float g_qkv[MTOK * 3 * Cc];      // qkv projections   [B,Tp,3C]
__device__ float g_kv[Bn * Hh * DHd * DHd];
__device__ float g_z[Bn * Hh * DHd];
__device__ float g_kvp[KVCH][Bn * Hh][DHd * DHd];
__device__ float g_zp[KVCH][Bn * Hh][DHd];
__device__ float g_pool[Bn * Cc];

// pre-split hi/lo half buffers (A operands) — 16B-aligned for cp.async sources
__device__ __align__(16) __half g_hnh[MTOK * Cc],  g_hnl[MTOK * Cc];    // LN output
__device__ __align__(16) __half g_yh[MTOK * Cc],   g_yl[MTOK * Cc];     // attention output
__device__ __align__(16) __half g_ffh[MTOK * DFFf], g_ffl[MTOK * DFFf]; // FFN hidden
// pre-split weights (B operands), all layers
__device__ __align__(16) __half g_wqh[Ll * 3 * Cc * Cc], g_wql[Ll * 3 * Cc * Cc];
__device__ __align__(16) __half g_woh[Ll * Cc * Cc],     g_wol[Ll * Cc * Cc];
__device__ __align__(16) __half g_w1h[Ll * DFFf * Cc],   g_w1l[Ll * DFFf * Cc];
__device__ __align__(16) __half g_w2h[Ll * Cc * DFFf],   g_w2l[Ll * Cc * DFFf];

__device__ __forceinline__ float gelu_f(float x) {
    return 0.5f * x * (1.0f + erff(x * 0.70710678118654752f));
}

__device__ __forceinline__ void split1(float v, __half& h, __half& l) {
    h = __float2half_rn(v);
    l = __float2half_rn(v - __half2float(h));
}

// ---------------- elementwise fp32 -> (hi, lo) fp16 split, float4-vectorized ----------------
__global__ __launch_bounds__(256) void split_f32(
    const float* __restrict__ s, __half* __restrict__ hi, __half* __restrict__ lo, int n4)
{
    int i = blockIdx.x * 256 + threadIdx.x;
    if (i >= n4) return;
    float4 v = ((const float4*)s)[i];
    __half h0, h1, h2, h3, l0, l1, l2, l3;
    split1(v.x, h0, l0); split1(v.y, h1, l1);
    split1(v.z, h2, l2); split1(v.w, h3, l3);
    ((__half2*)hi)[i * 2]     = __halves2half2(h0, h1);
    ((__half2*)hi)[i * 2 + 1] = __halves2half2(h2, h3);
    ((__half2*)lo)[i * 2]     = __halves2half2(l0, l1);
    ((__half2*)lo)[i * 2 + 1] = __halves2half2(l2, l3);
}

// ---------------- conv(k3,s2,p1) + BN(eval) + GELU + PE, writes g_h [B,Tp,C] ----------------
__global__ __launch_bounds__(256) void conv_bn_gelu_pe(
    const float* __restrict__ x, const float* __restrict__ w,
    const float* __restrict__ bng, const float* __restrict__ bnb)
{
    __shared__ float xs[NMm][65];
    const int b   = blockIdx.y;
    const int t0  = blockIdx.x * 32;
    const int tid = threadIdx.x;
    const int p0  = 2 * t0 - 1;

    for (int i = tid; i < NMm * 65; i += 256) {
        int m = i / 65, off = i % 65;
        int pos = p0 + off;
        float v = 0.f;
        if (pos >= 0 && pos < Tt) v = x[((size_t)b * NMm + m) * Tt + pos];
        xs[m][off] = v;
    }
    __syncthreads();

    const float LOG1E4 = 9.210340371976184f;
    for (int c = tid; c < Cc; c += 256) {
        float acc[32];
        #pragma unroll
        for (int t = 0; t < 32; t++) acc[t] = 0.f;
        const float* wc = w + (size_t)c * NMm * 3;
        for (int m = 0; m < NMm; m++) {
            float w0 = wc[m * 3 + 0], w1 = wc[m * 3 + 1], w2 = wc[m * 3 + 2];
            #pragma unroll
            for (int t = 0; t < 32; t++) {
                acc[t] += w0 * xs[m][2 * t] + w1 * xs[m][2 * t + 1] + w2 * xs[m][2 * t + 2];
            }
        }
        float scale = bng[c] * rsqrtf(1.0f + 1e-5f);
        float bias  = bnb[c];
        float freq  = expf(-(float)(c & ~1) * (LOG1E4 / (float)Cc));
        #pragma unroll
        for (int t = 0; t < 32; t++) {
            int tp = t0 + t;
            if (tp < TP) {
                float v = acc[t] * scale + bias;
                v = gelu_f(v);
                float ang = (float)tp * freq;
                v += (c & 1) ? cosf(ang) : sinf(ang);
                g_h[((size_t)b * TP + tp) * Cc + c] = v;
            }
        }
    }
}

// ---------------- LayerNorm over C=512 -> pre-split hi/lo halves ----------------
__global__ __launch_bounds__(128) void ln_kernel(
    const float* __restrict__ in, const float* __restrict__ g,
    const float* __restrict__ bb, __half* __restrict__ oh, __half* __restrict__ ol)
{
    const int tok = blockIdx.x;
    const int tid = threadIdx.x;
    const float* row = in + (size_t)tok * Cc;
    float4 v = *(const float4*)(row + tid * 4);
    float s  = v.x + v.y + v.z + v.w;
    float s2 = v.x * v.x + v.y * v.y + v.z * v.z + v.w * v.w;
    #pragma unroll
    for (int off = 16; off; off >>= 1) {
        s  += __shfl_xor_sync(0xffffffffu, s,  off);
        s2 += __shfl_xor_sync(0xffffffffu, s2, off);
    }
    __shared__ float ss[4], ssq[4];
    if ((tid & 31) == 0) { ss[tid >> 5] = s; ssq[tid >> 5] = s2; }
    __syncthreads();
    s  = ss[0] + ss[1] + ss[2] + ss[3];
    s2 = ssq[0] + ssq[1] + ssq[2] + ssq[3];
    float mean = s * (1.0f / Cc);
    float var  = s2 * (1.0f / Cc) - mean * mean;
    float rstd = rsqrtf(var + 1e-5f);
    int cb = tid * 4;
    float o0 = (v.x - mean) * rstd * g[cb + 0] + bb[cb + 0];
    float o1 = (v.y - mean) * rstd * g[cb + 1] + bb[cb + 1];
    float o2 = (v.z - mean) * rstd * g[cb + 2] + bb[cb + 2];
    float o3 = (v.w - mean) * rstd * g[cb + 3] + bb[cb + 3];
    __half h0, h1, h2, h3, l0, l1, l2, l3;
    split1(o0, h0, l0); split1(o1, h1, l1);
    split1(o2, h2, l2); split1(o3, h3, l3);
    size_t base = (size_t)tok * Cc + cb;
    *(__half2*)(oh + base)     = __halves2half2(h0, h1);
    *(__half2*)(oh + base + 2) = __halves2half2(h2, h3);
    *(__half2*)(ol + base)     = __halves2half2(l0, l1);
    *(__half2*)(ol + base + 2) = __halves2half2(l2, l3);
}

// ---------------- tensor-core NT GEMM consuming pre-split hi/lo halves ----------------
__device__ __forceinline__ void mma16816(float* c,
    uint32_t a0, uint32_t a1, uint32_t a2, uint32_t a3,
    uint32_t b0, uint32_t b1)
{
    asm volatile(
        "mma.sync.aligned.m16n8k16.row.col.f32.f16.f16.f32 "
        "{%0,%1,%2,%3}, {%4,%5,%6,%7}, {%8,%9}, {%0,%1,%2,%3};"
        : "+f"(c[0]), "+f"(c[1]), "+f"(c[2]), "+f"(c[3])
        : "r"(a0), "r"(a1), "r"(a2), "r"(a3), "r"(b0), "r"(b1));
}

__device__ __forceinline__ void cp16(uint32_t s_addr, const void* gmem) {
    asm volatile("cp.async.cg.shared.global [%0], [%1], 16;" :: "r"(s_addr), "l"(gmem));
}

// compute one K=16 tile: frag loads (validated addressing) + 48 HMMA
__device__ __forceinline__ void mma_tile(
    const __half (*sAh)[SPAD], const __half (*sAl)[SPAD],
    const __half (*sBh)[SPAD], const __half (*sBl)[SPAD],
    float acc[4][4][4], int wm, int wn, int g, int t2)
{
    uint32_t ah[4][4], al[4][4];
    #pragma unroll
    for (int mi = 0; mi < 4; mi++) {
        int r = wm * 64 + mi * 16 + g;
        ah[mi][0] = *(const uint32_t*)&sAh[r    ][t2    ];
        ah[mi][1] = *(const uint32_t*)&sAh[r + 8][t2    ];
        ah[mi][2] = *(const uint32_t*)&sAh[r    ][t2 + 8];
        ah[mi][3] = *(const uint32_t*)&sAh[r + 8][t2 + 8];
        al[mi][0] = *(const uint32_t*)&sAl[r    ][t2    ];
        al[mi][1] = *(const uint32_t*)&sAl[r + 8][t2    ];
        al[mi][2] = *(const uint32_t*)&sAl[r    ][t2 + 8];
        al[mi][3] = *(const uint32_t*)&sAl[r + 8][t2 + 8];
    }
    #pragma unroll
    for (int ni = 0; ni < 4; ni++) {
        int n = wn * 32 + ni * 8 + g;
        uint32_t bh0 = *(const uint32_t*)&sBh[n][t2    ];
        uint32_t bh1 = *(const uint32_t*)&sBh[n][t2 + 8];
        uint32_t bl0 = *(const uint32_t*)&sBl[n][t2    ];
        uint32_t bl1 = *(const uint32_t*)&sBl[n][t2 + 8];
        #pragma unroll
        for (int mi = 0; mi < 4; mi++) {
            mma16816(acc[mi][ni], ah[mi][0], ah[mi][1], ah[mi][2], ah[mi][3], bh0, bh1);
            mma16816(acc[mi][ni], ah[mi][0], ah[mi][1], ah[mi][2], ah[mi][3], bl0, bl1);
            mma16816(acc[mi][ni], al[mi][0], al[mi][1], al[mi][2], al[mi][3], bh0, bh1);
        }
    }
}

// C[M,N] = A @ B^T (+bias, opt GELU, opt +=C float, opt split-out halves)
// A,B pre-split hi/lo halves. 128x128 tile, BK=16, 256 thr, cp.async double-buffered.
template <int ACT, int RES, int SPLITOUT>
__global__ __launch_bounds__(256, 2) void gemm_nt_mma(
    const __half* __restrict__ Ahi, const __half* __restrict__ Alo,
    const __half* __restrict__ Bhi, const __half* __restrict__ Blo,
    const float* __restrict__ bias, float* __restrict__ C,
    __half* __restrict__ Chi, __half* __restrict__ Clo,
    int M, int N, int K)
{
    __shared__ __align__(16) __half sAh[2][128][SPAD], sAl[2][128][SPAD];
    __shared__ __align__(16) __half sBh[2][128][SPAD], sBl[2][128][SPAD];

    const int tid  = threadIdx.x;
    const int warp = tid >> 5, lane = tid & 31;
    const int wm = warp >> 2, wn = warp & 3;
    const int m0 = blockIdx.y * 128, n0 = blockIdx.x * 128;
    const int g  = lane >> 2;
    const int t2 = (lane & 3) << 1;

    const int lr  = tid >> 1;
    const int lcb = (tid & 1) << 3;                   // 0 or 8 (halves)
    const __half* Agh = Ahi + (size_t)(m0 + lr) * K + lcb;
    const __half* Agl = Alo + (size_t)(m0 + lr) * K + lcb;
    const __half* Bgh = Bhi + (size_t)(n0 + lr) * K + lcb;
    const __half* Bgl = Blo + (size_t)(n0 + lr) * K + lcb;

    uint32_t sa_h[2], sa_l[2], sb_h[2], sb_l[2];
    #pragma unroll
    for (int b = 0; b < 2; b++) {
        sa_h[b] = (uint32_t)__cvta_generic_to_shared(&sAh[b][lr][lcb]);
        sa_l[b] = (uint32_t)__cvta_generic_to_shared(&sAl[b][lr][lcb]);
        sb_h[b] = (uint32_t)__cvta_generic_to_shared(&sBh[b][lr][lcb]);
        sb_l[b] = (uint32_t)__cvta_generic_to_shared(&sBl[b][lr][lcb]);
    }

    float acc[4][4][4];
    #pragma unroll
    for (int mi = 0; mi < 4; mi++)
        #pragma unroll
        for (int ni = 0; ni < 4; ni++)
            #pragma unroll
            for (int r = 0; r < 4; r++) acc[mi][ni][r] = 0.f;

    // prologue: stage tile 0 into buffer 0
    cp16(sa_h[0], Agh); cp16(sa_l[0], Agl);
    cp16(sb_h[0], Bgh); cp16(sb_l[0], Bgl);
    asm volatile("cp.async.commit_group;");
    asm volatile("cp.async.wait_group 0;");
    __syncthreads();

    int buf = 0;
    for (int k0 = 16; k0 < K; k0 += 16) {
        int nb = buf ^ 1;
        cp16(sa_h[nb], Agh + k0); cp16(sa_l[nb], Agl + k0);
        cp16(sb_h[nb], Bgh + k0); cp16(sb_l[nb], Bgl + k0);
        asm volatile("cp.async.commit_group;");

        mma_tile(sAh[buf], sAl[buf], sBh[buf], sBl[buf], acc, wm, wn, g, t2);

        asm volatile("cp.async.wait_group 0;");
        __syncthreads();
        buf = nb;
    }
    mma_tile(sAh[buf], sAl[buf], sBh[buf], sBl[buf], acc, wm, wn, g, t2);

    // epilogue
    #pragma unroll
    for (int mi = 0; mi < 4; mi++) {
        #pragma unroll
        for (int ni = 0; ni < 4; ni++) {
            int R0 = m0 + wm * 64 + mi * 16 + g;
            int CB = n0 + wn * 32 + ni * 8 + t2;
            float bx = bias[CB], by = bias[CB + 1];
            float2 p0, p1;
            p0.x = acc[mi][ni][0] + bx; p0.y = acc[mi][ni][1] + by;
            p1.x = acc[mi][ni][2] + bx; p1.y = acc[mi][ni][3] + by;
            if (ACT) {
                p0.x = gelu_f(p0.x); p0.y = gelu_f(p0.y);
                p1.x = gelu_f(p1.x); p1.y = gelu_f(p1.y);
            }
            if (SPLITOUT) {
                __half h0, h1, l0, l1;
                split1(p0.x, h0, l0); split1(p0.y, h1, l1);
                *(__half2*)(Chi + (size_t)R0 * N + CB) = __halves2half2(h0, h1);
                *(__half2*)(Clo + (size_t)R0 * N + CB) = __halves2half2(l0, l1);
                split1(p1.x, h0, l0); split1(p1.y, h1, l1);
                *(__half2*)(Chi + (size_t)(R0 + 8) * N + CB) = __halves2half2(h0, h1);
                *(__half2*)(Clo + (size_t)(R0 + 8) * N + CB) = __halves2half2(l0, l1);
            } else {
                float* c0p = C + (size_t)R0 * N + CB;
                float* c1p = C + (size_t)(R0 + 8) * N + CB;
                if (RES) {
                    float2 o0 = *(const float2*)c0p;
                    float2 o1 = *(const float2*)c1p;
                    p0.x += o0.x; p0.y += o0.y;
                    p1.x += o1.x; p1.y += o1.y;
                }
                *(float2*)c0p = p0;
                *(float2*)c1p = p1;
            }
        }
    }
}

// ---------------- linear-attention state partials over time chunks ----------------
__global__ __launch_bounds__(256) void attn_kv_partial(const int* __restrict__ lengths)
{
    const int bh = blockIdx.x;
    const int ch = blockIdx.y;
    const int b = bh >> 3, hd = bh & 7;
    const int lenb = (lengths[b] + 1) >> 1;
    const int c0 = ch * KVCS;
    const int c1 = (c0 + KVCS < TP) ? c0 + KVCS : TP;
    __shared__ float kfs[32][64];
    __shared__ float vsm[32][64];
    const int tid = threadIdx.x;
    const int d0 = (tid & 15) << 2, e0 = (tid >> 4) << 2;

    float acc[4][4];
    float zacc[4];
    #pragma unroll
    for (int i = 0; i < 4; i++) {
        zacc[i] = 0.f;
        #pragma unroll
        for (int j = 0; j < 4; j++) acc[i][j] = 0.f;
    }

    for (int t0 = c0; t0 < c1; t0 += 32) {
        __syncthreads();
        for (int i = tid; i < 2048; i += 256) {
            int t = t0 + (i >> 6);
            int d = i & 63;
            float kf = 0.f, vv = 0.f;
            if (t < lenb && t < c1) {
                const float* row = g_qkv + ((size_t)(b * TP + t)) * 1536 + hd * 64;
                float kr = row[512 + d];
                kf = (kr > 0.f) ? kr + 1.f : expf(kr);
                vv = row[1024 + d];
            }
            kfs[i >> 6][d] = kf;
            vsm[i >> 6][d] = vv;
        }
        __syncthreads();
        #pragma unroll 8
        for (int t = 0; t < 32; t++) {
            float kf4[4], v4[4];
            *(float4*)kf4 = *(const float4*)&kfs[t][d0];
            *(float4*)v4  = *(const float4*)&vsm[t][e0];
            #pragma unroll
            for (int i = 0; i < 4; i++)
                #pragma unroll
                for (int j = 0; j < 4; j++)
                    acc[i][j] += kf4[i] * v4[j];
            if (e0 == 0) {
                #pragma unroll
                for (int i = 0; i < 4; i++) zacc[i] += kf4[i];
            }
        }
    }

    float* kvp = g_kvp[ch][bh];
    #pragma unroll
    for (int i = 0; i < 4; i++)
        #pragma unroll
        for (int j = 0; j < 4; j++)
            kvp[(d0 + i) * 64 + e0 + j] = acc[i][j];
    if (e0 == 0) {
        #pragma unroll
        for (int i = 0; i < 4; i++) g_zp[ch][bh][d0 + i] = zacc[i];
    }
}

__global__ __launch_bounds__(256) void attn_kv_reduce()
{
    const int bh = blockIdx.x;
    const int tid = threadIdx.x;
    for (int i = tid; i < DHd * DHd; i += 256) {
        float s = 0.f;
        #pragma unroll
        for (int c = 0; c < KVCH; c++) s += g_kvp[c][bh][i];
        g_kv[(size_t)bh * 4096 + i] = s;
    }
    if (tid < DHd) {
        float s = 0.f;
        #pragma unroll
        for (int c = 0; c < KVCH; c++) s += g_zp[c][bh][tid];
        g_z[bh * DHd + tid] = s;
    }
}

// ---------------- y = (qf @ kv) / max(qf.z, eps) -> pre-split hi/lo halves ----------------
__global__ __launch_bounds__(256) void attn_y()
{
    const int bh = blockIdx.y;
    const int b = bh >> 3, hd = bh & 7;
    const int t0 = blockIdx.x * 32;
    __shared__ float kvs[4096];
    __shared__ float zs[64];
    for (int i = threadIdx.x; i < 4096; i += 256) kvs[i] = g_kv[(size_t)bh * 4096 + i];
    if (threadIdx.x < 64) zs[threadIdx.x] = g_z[bh * 64 + threadIdx.x];
    __syncthreads();

    const int warp = threadIdx.x >> 5, lane = threadIdx.x & 31;
    for (int tt = 0; tt < 4; tt++) {
        int t = t0 + warp + (tt << 3);
        if (t >= TP) continue;
        const float* row = g_qkv + (size_t)(b * TP + t) * 1536 + hd * 64;
        float qa = row[lane];
        qa = (qa > 0.f) ? qa + 1.f : expf(qa);
        float qb = row[lane + 32];
        qb = (qb > 0.f) ? qb + 1.f : expf(qb);

        float den = qa * zs[lane] + qb * zs[lane + 32];
        #pragma unroll
        for (int off = 16; off; off >>= 1) den += __shfl_xor_sync(0xffffffffu, den, off);
        den = fmaxf(den, 1e-6f);
        float inv = 1.0f / den;

        float n0 = 0.f, n1 = 0.f;
        #pragma unroll
        for (int d = 0; d < 32; d++) {
            float qv = __shfl_sync(0xffffffffu, qa, d);
            n0 += qv * kvs[d * 64 + lane];
            n1 += qv * kvs[d * 64 + 32 + lane];
        }
        #pragma unroll
        for (int d = 0; d < 32; d++) {
            float qv = __shfl_sync(0xffffffffu, qb, d);
            n0 += qv * kvs[(d + 32) * 64 + lane];
            n1 += qv * kvs[(d + 32) * 64 + 32 + lane];
        }
        size_t base = (size_t)(b * TP + t) * Cc + hd * 64;
        float r0 = n0 * inv, r1 = n1 * inv;
        __half h, l;
        split1(r0, h, l);
        g_yh[base + lane] = h;       g_yl[base + lane] = l;
        split1(r1, h, l);
        g_yh[base + lane + 32] = h;  g_yl[base + lane + 32] = l;
    }
}

// ---------------- masked mean pool over time ----------------
__global__ __launch_bounds__(512) void pool_kernel(const int* __restrict__ lengths)
{
    const int b = blockIdx.x, c = threadIdx.x;
    const int lenb = (lengths[b] + 1) >> 1;
    const float* p = g_h + (size_t)b * TP * Cc + c;
    float s = 0.f;
    for (int t = 0; t < lenb; t++) s += p[(size_t)t * Cc];
    g_pool[b * Cc + c] = s / (float)lenb;
}

// ---------------- final FC ----------------
__global__ __launch_bounds__(128) void fc_kernel(
    const float* __restrict__ fw, const float* __restrict__ fb, float* __restrict__ out)
{
    const int tid = threadIdx.x;
    const int b = tid >> 3, n = tid & 7;
    const float* p  = g_pool + b * Cc;
    const float* wr = fw + n * Cc;
    float acc = 0.f;
    for (int k = 0; k < Cc; k++) acc += p[k] * wr[k];
    out[b * NCc + n] = acc + fb[n];
}

// ---------------- launch ----------------
extern "C" void kernel_launch(void* const* d_in, const int* in_sizes, int n_in,
                              void* d_out, int out_size)
{
    (void)in_sizes; (void)n_in; (void)out_size;
    const float* x       = (const float*)d_in[0];
    const int*   lengths = (const int*)  d_in[1];
    const float* conv_w  = (const float*)d_in[2];
    const float* bn_g    = (const float*)d_in[3];
    const float* bn_b    = (const float*)d_in[4];
    const float* qkv_w   = (const float*)d_in[5];
    const float* qkv_b   = (const float*)d_in[6];
    const float* out_w   = (const float*)d_in[7];
    const float* out_b   = (const float*)d_in[8];
    const float* lin1_w  = (const float*)d_in[9];
    const float* lin1_b  = (const float*)d_in[10];
    const float* lin2_w  = (const float*)d_in[11];
    const float* lin2_b  = (const float*)d_in[12];
    const float* ln1_g   = (const float*)d_in[13];
    const float* ln1_b   = (const float*)d_in[14];
    const float* ln2_g   = (const float*)d_in[15];
    const float* ln2_b   = (const float*)d_in[16];
    const float* fc_w    = (const float*)d_in[17];
    const float* fc_b    = (const float*)d_in[18];
    float* out = (float*)d_out;

    float *h;
    __half *hnh, *hnl, *yh, *yl, *ffh, *ffl;
    __half *wqh, *wql, *woh, *wol, *w1h, *w1l, *w2h, *w2l;
    cudaGetSymbolAddress((void**)&h,   g_h);
    cudaGetSymbolAddress((void**)&hnh, g_hnh); cudaGetSymbolAddress((void**)&hnl, g_hnl);
    cudaGetSymbolAddress((void**)&yh,  g_yh);  cudaGetSymbolAddress((void**)&yl,  g_yl);
    cudaGetSymbolAddress((void**)&ffh, g_ffh); cudaGetSymbolAddress((void**)&ffl, g_ffl);
    cudaGetSymbolAddress((void**)&wqh, g_wqh); cudaGetSymbolAddress((void**)&wql, g_wql);
    cudaGetSymbolAddress((void**)&woh, g_woh); cudaGetSymbolAddress((void**)&wol, g_wol);
    cudaGetSymbolAddress((void**)&w1h, g_w1h); cudaGetSymbolAddress((void**)&w1l, g_w1l);
    cudaGetSymbolAddress((void**)&w2h, g_w2h); cudaGetSymbolAddress((void**)&w2l, g_w2l);

    float* qkv;
    cudaGetSymbolAddress((void**)&qkv, g_qkv);

    // conv + BN + GELU + positional encoding -> g_h
    conv_bn_gelu_pe<<<dim3(63, Bn), 256>>>(x, conv_w, bn_g, bn_b);

    // pre-split all weights (hi/lo fp16), once per call
    {
        int n;
        n = Ll * 3 * Cc * Cc / 4; split_f32<<<(n + 255) / 256, 256>>>(qkv_w,  wqh, wql, n);
        n = Ll * Cc * Cc / 4;     split_f32<<<(n + 255) / 256, 256>>>(out_w,  woh, wol, n);
        n = Ll * DFFf * Cc / 4;   split_f32<<<(n + 255) / 256, 256>>>(lin1_w, w1h, w1l, n);
        n = Ll * Cc * DFFf / 4;   split_f32<<<(n + 255) / 256, 256>>>(lin2_w, w2h, w2l, n);
    }

    for (int l = 0; l < Ll; l++) {
        // --- pre-norm linear attention ---
        ln_kernel<<<MTOK, 128>>>(h, ln1_g + l * Cc, ln1_b + l * Cc, hnh, hnl);
        gemm_nt_mma<0, 0, 0><<<dim3(12, 250), 256>>>(
            hnh, hnl, wqh + (size_t)l * 3 * Cc * Cc, wql + (size_t)l * 3 * Cc * Cc,
            qkv_b + (size_t)l * 3 * Cc, qkv, (__half*)0, (__half*)0, MTOK, 3 * Cc, Cc);
        attn_kv_partial<<<dim3(Bn * Hh, KVCH), 256>>>(lengths);
        attn_kv_reduce<<<Bn * Hh, 256>>>();
        attn_y<<<dim3(63, Bn * Hh), 256>>>();
        gemm_nt_mma<0, 1, 0><<<dim3(4, 250), 256>>>(
            yh, yl, woh + (size_t)l * Cc * Cc, wol + (size_t)l * Cc * Cc,
            out_b + (size_t)l * Cc, h, (__half*)0, (__half*)0, MTOK, Cc, Cc);   // h += proj(y)
        // --- pre-norm FFN ---
        ln_kernel<<<MTOK, 128>>>(h, ln2_g + l * Cc, ln2_b + l * Cc, hnh, hnl);
        gemm_nt_mma<1, 0, 1><<<dim3(16, 250), 256>>>(
            hnh, hnl, w1h + (size_t)l * DFFf * Cc, w1l + (size_t)l * DFFf * Cc,
            lin1_b + (size_t)l * DFFf, (float*)0, ffh, ffl, MTOK, DFFf, Cc);    // gelu, split-out
        gemm_nt_mma<0, 1, 0><<<dim3(4, 250), 256>>>(
            ffh, ffl, w2h + (size_t)l * Cc * DFFf, w2l + (size_t)l * Cc * DFFf,
            lin2_b + (size_t)l * Cc, h, (__half*)0, (__half*)0, MTOK, Cc, DFFf); // h += ffn
    }

    pool_kernel<<<Bn, 512>>>(lengths);
    fc_kernel<<<1, 128>>>(fc_w, fc_b, out);
}